// round 8
// baseline (speedup 1.0000x reference)
#include <cuda_runtime.h>
#include <cstdint>

#define N_NODES_MAX 50000
#define E_MAX 800000
#define FDIM 64
#define HDIM 128

// Scratch (no allocations allowed in kernel_launch)
__device__ __align__(16) float g_h[(size_t)N_NODES_MAX * FDIM];  // h = (1+eps)x + agg
__device__ int g_cnt[N_NODES_MAX];        // per-node in-degree
__device__ int g_off[N_NODES_MAX + 1];    // CSR offsets
__device__ int g_pos[N_NODES_MAX];        // running positions for reorder
__device__ int g_scol[E_MAX];             // neighbor (col) ids sorted by row

// ---------------------------------------------------------------------------
// 1) zero histogram counters
// ---------------------------------------------------------------------------
__global__ void zero_cnt_kernel(int n) {
    int i = blockIdx.x * blockDim.x + threadIdx.x;
    if (i < n) g_cnt[i] = 0;
}

// ---------------------------------------------------------------------------
// 2) histogram of destination rows
// ---------------------------------------------------------------------------
__global__ void hist_kernel(const int* __restrict__ ei, int E) {
    int e = blockIdx.x * blockDim.x + threadIdx.x;
    if (e < E) atomicAdd(&g_cnt[ei[e]], 1);
}

// ---------------------------------------------------------------------------
// 3) exclusive prefix sum over counts (single block, 1024 threads)
//    writes g_off[0..n] and initializes g_pos = g_off
// ---------------------------------------------------------------------------
__global__ __launch_bounds__(1024) void scan_kernel(int n) {
    __shared__ int tsum[1024];
    int tid = threadIdx.x;
    int chunk = (n + 1023) >> 10;
    int beg = tid * chunk;
    int end = min(beg + chunk, n);

    int s = 0;
    for (int i = beg; i < end; i++) s += g_cnt[i];
    tsum[tid] = s;
    __syncthreads();

    // Hillis-Steele inclusive scan over 1024 thread sums
    for (int offs = 1; offs < 1024; offs <<= 1) {
        int v = (tid >= offs) ? tsum[tid - offs] : 0;
        __syncthreads();
        tsum[tid] += v;
        __syncthreads();
    }

    int run = tsum[tid] - s;   // exclusive prefix of this thread's chunk
    for (int i = beg; i < end; i++) {
        int c = g_cnt[i];
        g_off[i] = run;
        g_pos[i] = run;
        run += c;
    }
    if (tid == 1023) g_off[n] = run;   // == E
}

// ---------------------------------------------------------------------------
// 4) place neighbor ids into row-sorted order
// ---------------------------------------------------------------------------
__global__ void reorder_kernel(const int* __restrict__ ei, int E) {
    int e = blockIdx.x * blockDim.x + threadIdx.x;
    if (e < E) {
        int r = ei[e];
        int p = atomicAdd(&g_pos[r], 1);
        g_scol[p] = ei[E + e];
    }
}

// ---------------------------------------------------------------------------
// 5) aggregate: h[node] = (1+eps)*x[node] + sum_{c in nbrs(node)} x[c]
//    One warp per node; lane owns float2 (2 of 64 dims). Pure gather, no
//    atomics; x (12.8 MB) is L2-resident.
// ---------------------------------------------------------------------------
__global__ __launch_bounds__(256) void agg_kernel(const float* __restrict__ x,
                                                  const float* __restrict__ eps,
                                                  int N) {
    int node = blockIdx.x * 8 + (threadIdx.x >> 5);
    int lane = threadIdx.x & 31;
    if (node >= N) return;

    int s0 = __ldg(&g_off[node]);
    int s1 = __ldg(&g_off[node + 1]);
    const float2* x2 = (const float2*)x;

    float2 a0 = make_float2(0.f, 0.f);
    float2 a1 = make_float2(0.f, 0.f);
    float2 a2 = make_float2(0.f, 0.f);
    float2 a3 = make_float2(0.f, 0.f);
    int j = s0;
    for (; j + 4 <= s1; j += 4) {
        int c0 = __ldg(&g_scol[j]),     c1 = __ldg(&g_scol[j + 1]);
        int c2 = __ldg(&g_scol[j + 2]), c3 = __ldg(&g_scol[j + 3]);
        float2 v0 = x2[(size_t)c0 * 32 + lane];
        float2 v1 = x2[(size_t)c1 * 32 + lane];
        float2 v2 = x2[(size_t)c2 * 32 + lane];
        float2 v3 = x2[(size_t)c3 * 32 + lane];
        a0.x += v0.x; a0.y += v0.y;
        a1.x += v1.x; a1.y += v1.y;
        a2.x += v2.x; a2.y += v2.y;
        a3.x += v3.x; a3.y += v3.y;
    }
    for (; j < s1; j++) {
        int c = __ldg(&g_scol[j]);
        float2 v = x2[(size_t)c * 32 + lane];
        a0.x += v.x; a0.y += v.y;
    }
    float2 acc = make_float2((a0.x + a1.x) + (a2.x + a3.x),
                             (a0.y + a1.y) + (a2.y + a3.y));

    float s = 1.0f + __ldg(eps);
    float2 xv = x2[(size_t)node * 32 + lane];
    float2 h;
    h.x = fmaf(s, xv.x, acc.x);
    h.y = fmaf(s, xv.y, acc.y);
    ((float2*)g_h)[(size_t)node * 32 + lane] = h;
}

// ---------------------------------------------------------------------------
// Fused MLP: out = relu(h@W1+b1)@W2 + b2  (3xTF32 compensation, fp32 acc)
// 128 nodes/block, 256 threads = 8 warps, 1 m16 tile per warp.
// W1/W2 hi+lo pre-packed in b-fragment order -> one LDS.128 per (kt,nt).
// ---------------------------------------------------------------------------
#define SH   68
#define SHD  132
#define SM_W1P 0
#define SM_W2P 16384
#define SM_ACT 32768
#define SM_TOTAL_U32 (SM_ACT + 128 * SHD)   // 49664 u32 = 198656 B

__device__ __forceinline__ unsigned f2tf32(float x) {
    unsigned u;
    asm("cvt.rna.tf32.f32 %0, %1;" : "=r"(u) : "f"(x));
    return u;
}

__device__ __forceinline__ void mma8(float* d, const unsigned* a, const unsigned* b) {
    asm volatile(
        "mma.sync.aligned.m16n8k8.row.col.f32.tf32.tf32.f32 "
        "{%0,%1,%2,%3}, {%4,%5,%6,%7}, {%8,%9}, {%0,%1,%2,%3};\n"
        : "+f"(d[0]), "+f"(d[1]), "+f"(d[2]), "+f"(d[3])
        : "r"(a[0]), "r"(a[1]), "r"(a[2]), "r"(a[3]), "r"(b[0]), "r"(b[1]));
}

__device__ __forceinline__ uint4 pack_hilo(float f0, float f1) {
    uint4 u;
    u.x = f2tf32(f0);
    u.y = f2tf32(f1);
    u.z = f2tf32(f0 - __uint_as_float(u.x));
    u.w = f2tf32(f1 - __uint_as_float(u.y));
    return u;
}

__global__ __launch_bounds__(256, 1)
void fused_mlp_kernel(const float* __restrict__ W1, const float* __restrict__ b1,
                      const float* __restrict__ W2, const float* __restrict__ b2,
                      float* __restrict__ out, int N) {
    extern __shared__ unsigned smu[];
    uint4* W1p = (uint4*)(smu + SM_W1P);
    uint4* W2p = (uint4*)(smu + SM_W2P);
    float* hsm = (float*)(smu + SM_ACT);     // stride SH
    float* hid = (float*)(smu + SM_ACT);     // stride SHD (aliases hsm)

    const int tid  = threadIdx.x;
    const int lane = tid & 31;
    const int wid  = tid >> 5;
    const int g = lane >> 2;
    const int t = lane & 3;
    const int nb = blockIdx.x * 128;
    const int wm = wid * 16;

    // ---- pack W1 hi/lo in b-frag order ----
#pragma unroll 4
    for (int idx = tid; idx < 8 * 16 * 32; idx += 256) {
        int li = idx & 31;
        int nt = (idx >> 5) & 15;
        int kt = idx >> 9;
        int k0 = kt * 8 + (li & 3);
        int n  = nt * 8 + (li >> 2);
        W1p[idx] = pack_hilo(W1[k0 * HDIM + n], W1[(k0 + 4) * HDIM + n]);
    }
    // ---- pack W2 hi/lo ----
#pragma unroll 4
    for (int idx = tid; idx < 16 * 8 * 32; idx += 256) {
        int li = idx & 31;
        int nt = (idx >> 5) & 7;
        int kt = idx >> 8;
        int k0 = kt * 8 + (li & 3);
        int n  = nt * 8 + (li >> 2);
        W2p[idx] = pack_hilo(W2[k0 * FDIM + n], W2[(k0 + 4) * FDIM + n]);
    }
    // ---- load h tile from g_h ----
#pragma unroll 4
    for (int i = tid; i < 128 * 16; i += 256) {
        int r = i >> 4, c4 = i & 15;
        int node = nb + r;
        float4 v = make_float4(0.f, 0.f, 0.f, 0.f);
        if (node < N) v = ((const float4*)(g_h + (size_t)node * FDIM))[c4];
        ((float4*)(hsm + r * SH))[c4] = v;
    }
    __syncthreads();

    // =================== Stage 1: hid = relu(h @ W1 + b1) ===================
    float acc1[16][4];
#pragma unroll
    for (int nt = 0; nt < 16; nt++) {
        float2 bv = *(const float2*)(b1 + nt * 8 + 2 * t);
        acc1[nt][0] = bv.x; acc1[nt][1] = bv.y;
        acc1[nt][2] = bv.x; acc1[nt][3] = bv.y;
    }

#pragma unroll 1
    for (int kt = 0; kt < 8; kt++) {
        int r0 = (wm + g) * SH;
        int r1 = (wm + g + 8) * SH;
        int c0 = kt * 8 + t;
        float f0 = hsm[r0 + c0],     f1 = hsm[r1 + c0];
        float f2 = hsm[r0 + c0 + 4], f3 = hsm[r1 + c0 + 4];
        unsigned ah[4], al[4];
        ah[0] = f2tf32(f0); al[0] = f2tf32(f0 - __uint_as_float(ah[0]));
        ah[1] = f2tf32(f1); al[1] = f2tf32(f1 - __uint_as_float(ah[1]));
        ah[2] = f2tf32(f2); al[2] = f2tf32(f2 - __uint_as_float(ah[2]));
        ah[3] = f2tf32(f3); al[3] = f2tf32(f3 - __uint_as_float(ah[3]));
        const uint4* wrow = W1p + (kt * 16) * 32 + lane;
#pragma unroll
        for (int nt = 0; nt < 16; nt++) {
            uint4 w = wrow[nt * 32];
            unsigned bh[2] = {w.x, w.y}, bl[2] = {w.z, w.w};
            mma8(acc1[nt], ah, bh);
            mma8(acc1[nt], ah, bl);
            mma8(acc1[nt], al, bh);
        }
    }

    __syncthreads();   // done reading hsm; safe to overwrite with hid

    {
        int r0 = (wm + g) * SHD;
        int r1 = (wm + g + 8) * SHD;
#pragma unroll
        for (int nt = 0; nt < 16; nt++) {
            int c = nt * 8 + 2 * t;
            *(float2*)(hid + r0 + c) =
                make_float2(fmaxf(acc1[nt][0], 0.f), fmaxf(acc1[nt][1], 0.f));
            *(float2*)(hid + r1 + c) =
                make_float2(fmaxf(acc1[nt][2], 0.f), fmaxf(acc1[nt][3], 0.f));
        }
    }
    __syncwarp();      // hid rows are warp-private

    // =================== Stage 2: out = hid @ W2 + b2 ===================
    float acc2[8][4];
#pragma unroll
    for (int nt = 0; nt < 8; nt++) {
        float2 bv = *(const float2*)(b2 + nt * 8 + 2 * t);
        acc2[nt][0] = bv.x; acc2[nt][1] = bv.y;
        acc2[nt][2] = bv.x; acc2[nt][3] = bv.y;
    }

#pragma unroll 1
    for (int kt = 0; kt < 16; kt++) {
        int r0 = (wm + g) * SHD;
        int r1 = (wm + g + 8) * SHD;
        int c0 = kt * 8 + t;
        float f0 = hid[r0 + c0],     f1 = hid[r1 + c0];
        float f2 = hid[r0 + c0 + 4], f3 = hid[r1 + c0 + 4];
        unsigned ah[4], al[4];
        ah[0] = f2tf32(f0); al[0] = f2tf32(f0 - __uint_as_float(ah[0]));
        ah[1] = f2tf32(f1); al[1] = f2tf32(f1 - __uint_as_float(ah[1]));
        ah[2] = f2tf32(f2); al[2] = f2tf32(f2 - __uint_as_float(ah[2]));
        ah[3] = f2tf32(f3); al[3] = f2tf32(f3 - __uint_as_float(ah[3]));
        const uint4* wrow = W2p + (kt * 8) * 32 + lane;
#pragma unroll
        for (int nt = 0; nt < 8; nt++) {
            uint4 w = wrow[nt * 32];
            unsigned bh[2] = {w.x, w.y}, bl[2] = {w.z, w.w};
            mma8(acc2[nt], ah, bh);
            mma8(acc2[nt], ah, bl);
            mma8(acc2[nt], al, bh);
        }
    }

    // ---- write output ----
    {
        int node0 = nb + wm + g;
        int node1 = node0 + 8;
#pragma unroll
        for (int nt = 0; nt < 8; nt++) {
            int c = nt * 8 + 2 * t;
            if (node0 < N)
                *(float2*)(out + (size_t)node0 * FDIM + c) =
                    make_float2(acc2[nt][0], acc2[nt][1]);
            if (node1 < N)
                *(float2*)(out + (size_t)node1 * FDIM + c) =
                    make_float2(acc2[nt][2], acc2[nt][3]);
        }
    }
}

// ---------------------------------------------------------------------------
extern "C" void kernel_launch(void* const* d_in, const int* in_sizes, int n_in,
                              void* d_out, int out_size) {
    const float* x   = (const float*)d_in[0];
    const int*   ei  = (const int*)d_in[1];      // int32 (jax x64 disabled)
    const float* W1  = (const float*)d_in[2];
    const float* b1  = (const float*)d_in[3];
    const float* W2  = (const float*)d_in[4];
    const float* b2  = (const float*)d_in[5];
    const float* eps = (const float*)d_in[6];
    float* out = (float*)d_out;

    int N = in_sizes[0] / FDIM;       // 50000
    int E = in_sizes[1] / 2;          // 800000

    zero_cnt_kernel<<<(N + 255) / 256, 256>>>(N);
    hist_kernel<<<(E + 255) / 256, 256>>>(ei, E);
    scan_kernel<<<1, 1024>>>(N);
    reorder_kernel<<<(E + 255) / 256, 256>>>(ei, E);
    agg_kernel<<<(N + 7) / 8, 256>>>(x, eps, N);

    cudaFuncSetAttribute(fused_mlp_kernel,
                         cudaFuncAttributeMaxDynamicSharedMemorySize,
                         SM_TOTAL_U32 * (int)sizeof(unsigned));
    fused_mlp_kernel<<<(N + 127) / 128, 256, SM_TOTAL_U32 * sizeof(unsigned)>>>(
        W1, b1, W2, b2, out, N);
}

// round 10
// speedup vs baseline: 2.5652x; 2.5652x over previous
#include <cuda_runtime.h>
#include <cstdint>

#define N_NODES_MAX 50000
#define FDIM 64
#define HDIM 128
#define NREP 2

// Scratch (no allocations allowed in kernel_launch)
// Two replicas of the aggregation target to halve L2 atomic contention.
__device__ __align__(16) float g_hr[NREP][(size_t)N_NODES_MAX * FDIM];

// ---------------------------------------------------------------------------
// Scatter-add with replica split: edge e accumulates into replica e&1.
// Thread = (edge, 16B chunk). edge_index is int32.
// ---------------------------------------------------------------------------
__global__ void scatter_kernel(const float* __restrict__ x,
                               const int* __restrict__ ei, int E) {
    long long i = (long long)blockIdx.x * blockDim.x + threadIdx.x;
    if (i >= (long long)E * 16) return;
    int e = (int)(i >> 4);
    int c = (int)(i & 15);
    int row = ei[e];
    int col = ei[E + e];
    float4 v = *(const float4*)(x + (size_t)col * FDIM + c * 4);
    float* dst = g_hr[e & 1] + (size_t)row * FDIM + c * 4;
    asm volatile("red.global.add.v4.f32 [%0], {%1,%2,%3,%4};"
                 :: "l"(dst), "f"(v.x), "f"(v.y), "f"(v.z), "f"(v.w)
                 : "memory");
}

// ---------------------------------------------------------------------------
// Fused MLP: out = relu(h@W1+b1)@W2 + b2,
// h = (1+eps)*x + g_hr[0] + g_hr[1]  (computed on load)
// 3xTF32 compensation (hi*hi + hi*lo + lo*hi), fp32 accumulate.
// 128 nodes/block, 256 threads = 8 warps, 1 m16 tile per warp.
// W1/W2 hi+lo pre-packed in b-fragment order -> one LDS.128 per (kt,nt).
// ---------------------------------------------------------------------------
#define SH   68
#define SHD  132
#define SM_W1P 0
#define SM_W2P 16384
#define SM_ACT 32768
#define SM_TOTAL_U32 (SM_ACT + 128 * SHD)   // 49664 u32 = 198656 B

__device__ __forceinline__ unsigned f2tf32(float x) {
    unsigned u;
    asm("cvt.rna.tf32.f32 %0, %1;" : "=r"(u) : "f"(x));
    return u;
}

__device__ __forceinline__ void mma8(float* d, const unsigned* a, const unsigned* b) {
    asm volatile(
        "mma.sync.aligned.m16n8k8.row.col.f32.tf32.tf32.f32 "
        "{%0,%1,%2,%3}, {%4,%5,%6,%7}, {%8,%9}, {%0,%1,%2,%3};\n"
        : "+f"(d[0]), "+f"(d[1]), "+f"(d[2]), "+f"(d[3])
        : "r"(a[0]), "r"(a[1]), "r"(a[2]), "r"(a[3]), "r"(b[0]), "r"(b[1]));
}

__device__ __forceinline__ uint4 pack_hilo(float f0, float f1) {
    uint4 u;
    u.x = f2tf32(f0);
    u.y = f2tf32(f1);
    u.z = f2tf32(f0 - __uint_as_float(u.x));
    u.w = f2tf32(f1 - __uint_as_float(u.y));
    return u;
}

__global__ __launch_bounds__(256, 1)
void fused_mlp_kernel(const float* __restrict__ x,
                      const float* __restrict__ W1, const float* __restrict__ b1,
                      const float* __restrict__ W2, const float* __restrict__ b2,
                      const float* __restrict__ eps,
                      float* __restrict__ out, int N) {
    extern __shared__ unsigned smu[];
    uint4* W1p = (uint4*)(smu + SM_W1P);
    uint4* W2p = (uint4*)(smu + SM_W2P);
    float* hsm = (float*)(smu + SM_ACT);     // stride SH
    float* hid = (float*)(smu + SM_ACT);     // stride SHD (aliases hsm)

    const int tid  = threadIdx.x;
    const int lane = tid & 31;
    const int wid  = tid >> 5;
    const int g = lane >> 2;
    const int t = lane & 3;
    const int nb = blockIdx.x * 128;
    const int wm = wid * 16;

    // ---- pack W1 hi/lo in b-frag order ----
#pragma unroll 4
    for (int idx = tid; idx < 8 * 16 * 32; idx += 256) {
        int li = idx & 31;
        int nt = (idx >> 5) & 15;
        int kt = idx >> 9;
        int k0 = kt * 8 + (li & 3);
        int n  = nt * 8 + (li >> 2);
        W1p[idx] = pack_hilo(W1[k0 * HDIM + n], W1[(k0 + 4) * HDIM + n]);
    }
    // ---- pack W2 hi/lo ----
#pragma unroll 4
    for (int idx = tid; idx < 16 * 8 * 32; idx += 256) {
        int li = idx & 31;
        int nt = (idx >> 5) & 7;
        int kt = idx >> 8;
        int k0 = kt * 8 + (li & 3);
        int n  = nt * 8 + (li >> 2);
        W2p[idx] = pack_hilo(W2[k0 * FDIM + n], W2[(k0 + 4) * FDIM + n]);
    }
    // ---- load h tile: h = (1+eps)*x + agg0 + agg1 ----
    {
        float s = 1.0f + __ldg(eps);
#pragma unroll 4
        for (int i = tid; i < 128 * 16; i += 256) {
            int r = i >> 4, c4 = i & 15;
            int node = nb + r;
            float4 v = make_float4(0.f, 0.f, 0.f, 0.f);
            if (node < N) {
                float4 a0 = ((const float4*)(g_hr[0] + (size_t)node * FDIM))[c4];
                float4 a1 = ((const float4*)(g_hr[1] + (size_t)node * FDIM))[c4];
                float4 xv = ((const float4*)(x       + (size_t)node * FDIM))[c4];
                v.x = fmaf(s, xv.x, a0.x + a1.x);
                v.y = fmaf(s, xv.y, a0.y + a1.y);
                v.z = fmaf(s, xv.z, a0.z + a1.z);
                v.w = fmaf(s, xv.w, a0.w + a1.w);
            }
            ((float4*)(hsm + r * SH))[c4] = v;
        }
    }
    __syncthreads();

    // =================== Stage 1: hid = relu(h @ W1 + b1) ===================
    float acc1[16][4];
#pragma unroll
    for (int nt = 0; nt < 16; nt++) {
        float2 bv = *(const float2*)(b1 + nt * 8 + 2 * t);
        acc1[nt][0] = bv.x; acc1[nt][1] = bv.y;
        acc1[nt][2] = bv.x; acc1[nt][3] = bv.y;
    }

#pragma unroll 1
    for (int kt = 0; kt < 8; kt++) {
        int r0 = (wm + g) * SH;
        int r1 = (wm + g + 8) * SH;
        int c0 = kt * 8 + t;
        float f0 = hsm[r0 + c0],     f1 = hsm[r1 + c0];
        float f2 = hsm[r0 + c0 + 4], f3 = hsm[r1 + c0 + 4];
        unsigned ah[4], al[4];
        ah[0] = f2tf32(f0); al[0] = f2tf32(f0 - __uint_as_float(ah[0]));
        ah[1] = f2tf32(f1); al[1] = f2tf32(f1 - __uint_as_float(ah[1]));
        ah[2] = f2tf32(f2); al[2] = f2tf32(f2 - __uint_as_float(ah[2]));
        ah[3] = f2tf32(f3); al[3] = f2tf32(f3 - __uint_as_float(ah[3]));
        const uint4* wrow = W1p + (kt * 16) * 32 + lane;
#pragma unroll
        for (int nt = 0; nt < 16; nt++) {
            uint4 w = wrow[nt * 32];
            unsigned bh[2] = {w.x, w.y}, bl[2] = {w.z, w.w};
            mma8(acc1[nt], ah, bh);
            mma8(acc1[nt], ah, bl);
            mma8(acc1[nt], al, bh);
        }
    }

    __syncthreads();   // done reading hsm; safe to overwrite with hid

    {
        int r0 = (wm + g) * SHD;
        int r1 = (wm + g + 8) * SHD;
#pragma unroll
        for (int nt = 0; nt < 16; nt++) {
            int c = nt * 8 + 2 * t;
            *(float2*)(hid + r0 + c) =
                make_float2(fmaxf(acc1[nt][0], 0.f), fmaxf(acc1[nt][1], 0.f));
            *(float2*)(hid + r1 + c) =
                make_float2(fmaxf(acc1[nt][2], 0.f), fmaxf(acc1[nt][3], 0.f));
        }
    }
    __syncwarp();      // hid rows are warp-private

    // =================== Stage 2: out = hid @ W2 + b2 ===================
    float acc2[8][4];
#pragma unroll
    for (int nt = 0; nt < 8; nt++) {
        float2 bv = *(const float2*)(b2 + nt * 8 + 2 * t);
        acc2[nt][0] = bv.x; acc2[nt][1] = bv.y;
        acc2[nt][2] = bv.x; acc2[nt][3] = bv.y;
    }

#pragma unroll 1
    for (int kt = 0; kt < 16; kt++) {
        int r0 = (wm + g) * SHD;
        int r1 = (wm + g + 8) * SHD;
        int c0 = kt * 8 + t;
        float f0 = hid[r0 + c0],     f1 = hid[r1 + c0];
        float f2 = hid[r0 + c0 + 4], f3 = hid[r1 + c0 + 4];
        unsigned ah[4], al[4];
        ah[0] = f2tf32(f0); al[0] = f2tf32(f0 - __uint_as_float(ah[0]));
        ah[1] = f2tf32(f1); al[1] = f2tf32(f1 - __uint_as_float(ah[1]));
        ah[2] = f2tf32(f2); al[2] = f2tf32(f2 - __uint_as_float(ah[2]));
        ah[3] = f2tf32(f3); al[3] = f2tf32(f3 - __uint_as_float(ah[3]));
        const uint4* wrow = W2p + (kt * 8) * 32 + lane;
#pragma unroll
        for (int nt = 0; nt < 8; nt++) {
            uint4 w = wrow[nt * 32];
            unsigned bh[2] = {w.x, w.y}, bl[2] = {w.z, w.w};
            mma8(acc2[nt], ah, bh);
            mma8(acc2[nt], ah, bl);
            mma8(acc2[nt], al, bh);
        }
    }

    // ---- write output ----
    {
        int node0 = nb + wm + g;
        int node1 = node0 + 8;
#pragma unroll
        for (int nt = 0; nt < 8; nt++) {
            int c = nt * 8 + 2 * t;
            if (node0 < N)
                *(float2*)(out + (size_t)node0 * FDIM + c) =
                    make_float2(acc2[nt][0], acc2[nt][1]);
            if (node1 < N)
                *(float2*)(out + (size_t)node1 * FDIM + c) =
                    make_float2(acc2[nt][2], acc2[nt][3]);
        }
    }
}

// ---------------------------------------------------------------------------
extern "C" void kernel_launch(void* const* d_in, const int* in_sizes, int n_in,
                              void* d_out, int out_size) {
    const float* x   = (const float*)d_in[0];
    const int*   ei  = (const int*)d_in[1];      // int32 (jax x64 disabled)
    const float* W1  = (const float*)d_in[2];
    const float* b1  = (const float*)d_in[3];
    const float* W2  = (const float*)d_in[4];
    const float* b2  = (const float*)d_in[5];
    const float* eps = (const float*)d_in[6];
    float* out = (float*)d_out;

    int N = in_sizes[0] / FDIM;       // 50000
    int E = in_sizes[1] / 2;          // 800000

    // Zero both replicas with one async memset (graph-capturable, no alloc).
    void* hr_ptr = nullptr;
    cudaGetSymbolAddress(&hr_ptr, g_hr);
    cudaMemsetAsync(hr_ptr, 0,
                    (size_t)NREP * N_NODES_MAX * FDIM * sizeof(float));

    long long sthreads = (long long)E * 16;
    int sblocks = (int)((sthreads + 255) / 256);
    scatter_kernel<<<sblocks, 256>>>(x, ei, E);

    cudaFuncSetAttribute(fused_mlp_kernel,
                         cudaFuncAttributeMaxDynamicSharedMemorySize,
                         SM_TOTAL_U32 * (int)sizeof(unsigned));
    fused_mlp_kernel<<<(N + 127) / 128, 256, SM_TOTAL_U32 * sizeof(unsigned)>>>(
        x, W1, b1, W2, b2, eps, out, N);
}

// round 12
// speedup vs baseline: 2.7872x; 1.0865x over previous
#include <cuda_runtime.h>
#include <cstdint>

#define N_NODES_MAX 50000
#define FDIM 64
#define HDIM 128
#define NREP 2

// Scratch (no allocations allowed in kernel_launch)
__device__ __align__(16) float g_hr[NREP][(size_t)N_NODES_MAX * FDIM];
__device__ __align__(16) uint4 g_W1p[8 * 16 * 32];   // W1 hi/lo b-frag packed
__device__ __align__(16) uint4 g_W2p[16 * 8 * 32];   // W2 hi/lo b-frag packed

// ---------------------------------------------------------------------------
// Scatter-add with replica split: edge e accumulates into replica e&1.
// ---------------------------------------------------------------------------
__global__ void scatter_kernel(const float* __restrict__ x,
                               const int* __restrict__ ei, int E) {
    long long i = (long long)blockIdx.x * blockDim.x + threadIdx.x;
    if (i >= (long long)E * 16) return;
    int e = (int)(i >> 4);
    int c = (int)(i & 15);
    int row = ei[e];
    int col = ei[E + e];
    float4 v = *(const float4*)(x + (size_t)col * FDIM + c * 4);
    float* dst = g_hr[e & 1] + (size_t)row * FDIM + c * 4;
    asm volatile("red.global.add.v4.f32 [%0], {%1,%2,%3,%4};"
                 :: "l"(dst), "f"(v.x), "f"(v.y), "f"(v.z), "f"(v.w)
                 : "memory");
}

// ---------------------------------------------------------------------------
// TF32 helpers
// ---------------------------------------------------------------------------
__device__ __forceinline__ unsigned f2tf32(float x) {
    unsigned u;
    asm("cvt.rna.tf32.f32 %0, %1;" : "=r"(u) : "f"(x));
    return u;
}

__device__ __forceinline__ void mma8(float* d, const unsigned* a, const unsigned* b) {
    asm volatile(
        "mma.sync.aligned.m16n8k8.row.col.f32.tf32.tf32.f32 "
        "{%0,%1,%2,%3}, {%4,%5,%6,%7}, {%8,%9}, {%0,%1,%2,%3};\n"
        : "+f"(d[0]), "+f"(d[1]), "+f"(d[2]), "+f"(d[3])
        : "r"(a[0]), "r"(a[1]), "r"(a[2]), "r"(a[3]), "r"(b[0]), "r"(b[1]));
}

__device__ __forceinline__ uint4 pack_hilo(float f0, float f1) {
    uint4 u;
    u.x = f2tf32(f0);
    u.y = f2tf32(f1);
    u.z = f2tf32(f0 - __uint_as_float(u.x));
    u.w = f2tf32(f1 - __uint_as_float(u.y));
    return u;
}

// ---------------------------------------------------------------------------
// One-off: pack W1/W2 hi+lo into b-fragment order in GLOBAL scratch.
// idx < 4096 -> W1 frag; else W2 frag.  (8192 threads total)
// ---------------------------------------------------------------------------
__global__ void pack_w_kernel(const float* __restrict__ W1,
                              const float* __restrict__ W2) {
    int idx = blockIdx.x * blockDim.x + threadIdx.x;
    if (idx < 8 * 16 * 32) {
        int li = idx & 31;
        int nt = (idx >> 5) & 15;
        int kt = idx >> 9;
        int k0 = kt * 8 + (li & 3);
        int n  = nt * 8 + (li >> 2);
        g_W1p[idx] = pack_hilo(W1[k0 * HDIM + n], W1[(k0 + 4) * HDIM + n]);
    } else {
        int j = idx - 8 * 16 * 32;
        if (j < 16 * 8 * 32) {
            int li = j & 31;
            int nt = (j >> 5) & 7;
            int kt = j >> 8;
            int k0 = kt * 8 + (li & 3);
            int n  = nt * 8 + (li >> 2);
            g_W2p[j] = pack_hilo(W2[k0 * FDIM + n], W2[(k0 + 4) * FDIM + n]);
        }
    }
}

// ---------------------------------------------------------------------------
// Fused MLP: out = relu(h@W1+b1)@W2 + b2,  h = (1+eps)*x + agg0 + agg1.
// 3xTF32 compensation, fp32 accumulate.
// 128 nodes/block, 256 threads = 8 warps, 1 m16 tile per warp.
// Weights: pre-packed fragments streamed from GLOBAL (L1/L2-resident,
// identical addresses across warps -> broadcast). smem = activations only
// (66 KB) -> 2 blocks/SM.
// ---------------------------------------------------------------------------
#define SH   68
#define SHD  132
#define SM_TOTAL_U32 (128 * SHD)     // 16896 u32 = 67584 B

__global__ __launch_bounds__(256, 2)
void fused_mlp_kernel(const float* __restrict__ x,
                      const float* __restrict__ b1,
                      const float* __restrict__ b2,
                      const float* __restrict__ eps,
                      float* __restrict__ out, int N) {
    extern __shared__ unsigned smu[];
    float* hsm = (float*)smu;        // stride SH during stage 1
    float* hid = (float*)smu;        // stride SHD during stage 2 (aliased)

    const int tid  = threadIdx.x;
    const int lane = tid & 31;
    const int wid  = tid >> 5;
    const int g = lane >> 2;
    const int t = lane & 3;
    const int nb = blockIdx.x * 128;
    const int wm = wid * 16;

    // ---- load h tile: h = (1+eps)*x + agg0 + agg1 ----
    {
        float s = 1.0f + __ldg(eps);
#pragma unroll 4
        for (int i = tid; i < 128 * 16; i += 256) {
            int r = i >> 4, c4 = i & 15;
            int node = nb + r;
            float4 v = make_float4(0.f, 0.f, 0.f, 0.f);
            if (node < N) {
                float4 a0 = ((const float4*)(g_hr[0] + (size_t)node * FDIM))[c4];
                float4 a1 = ((const float4*)(g_hr[1] + (size_t)node * FDIM))[c4];
                float4 xv = ((const float4*)(x       + (size_t)node * FDIM))[c4];
                v.x = fmaf(s, xv.x, a0.x + a1.x);
                v.y = fmaf(s, xv.y, a0.y + a1.y);
                v.z = fmaf(s, xv.z, a0.z + a1.z);
                v.w = fmaf(s, xv.w, a0.w + a1.w);
            }
            ((float4*)(hsm + r * SH))[c4] = v;
        }
    }
    __syncthreads();

    // =================== Stage 1: hid = relu(h @ W1 + b1) ===================
    float acc1[16][4];
#pragma unroll
    for (int nt = 0; nt < 16; nt++) {
        float2 bv = *(const float2*)(b1 + nt * 8 + 2 * t);
        acc1[nt][0] = bv.x; acc1[nt][1] = bv.y;
        acc1[nt][2] = bv.x; acc1[nt][3] = bv.y;
    }

#pragma unroll 1
    for (int kt = 0; kt < 8; kt++) {
        int r0 = (wm + g) * SH;
        int r1 = (wm + g + 8) * SH;
        int c0 = kt * 8 + t;
        float f0 = hsm[r0 + c0],     f1 = hsm[r1 + c0];
        float f2 = hsm[r0 + c0 + 4], f3 = hsm[r1 + c0 + 4];
        unsigned ah[4], al[4];
        ah[0] = f2tf32(f0); al[0] = f2tf32(f0 - __uint_as_float(ah[0]));
        ah[1] = f2tf32(f1); al[1] = f2tf32(f1 - __uint_as_float(ah[1]));
        ah[2] = f2tf32(f2); al[2] = f2tf32(f2 - __uint_as_float(ah[2]));
        ah[3] = f2tf32(f3); al[3] = f2tf32(f3 - __uint_as_float(ah[3]));
        const uint4* wrow = g_W1p + (kt * 16) * 32 + lane;
#pragma unroll
        for (int nt = 0; nt < 16; nt++) {
            uint4 w = __ldg(&wrow[nt * 32]);
            unsigned bh[2] = {w.x, w.y}, bl[2] = {w.z, w.w};
            mma8(acc1[nt], ah, bh);
            mma8(acc1[nt], ah, bl);
            mma8(acc1[nt], al, bh);
        }
    }

    __syncthreads();   // done reading hsm; safe to overwrite with hid

    {
        int r0 = (wm + g) * SHD;
        int r1 = (wm + g + 8) * SHD;
#pragma unroll
        for (int nt = 0; nt < 16; nt++) {
            int c = nt * 8 + 2 * t;
            *(float2*)(hid + r0 + c) =
                make_float2(fmaxf(acc1[nt][0], 0.f), fmaxf(acc1[nt][1], 0.f));
            *(float2*)(hid + r1 + c) =
                make_float2(fmaxf(acc1[nt][2], 0.f), fmaxf(acc1[nt][3], 0.f));
        }
    }
    __syncwarp();      // hid rows are warp-private

    // =================== Stage 2: out = hid @ W2 + b2 ===================
    float acc2[8][4];
#pragma unroll
    for (int nt = 0; nt < 8; nt++) {
        float2 bv = *(const float2*)(b2 + nt * 8 + 2 * t);
        acc2[nt][0] = bv.x; acc2[nt][1] = bv.y;
        acc2[nt][2] = bv.x; acc2[nt][3] = bv.y;
    }

#pragma unroll 1
    for (int kt = 0; kt < 16; kt++) {
        int r0 = (wm + g) * SHD;
        int r1 = (wm + g + 8) * SHD;
        int c0 = kt * 8 + t;
        float f0 = hid[r0 + c0],     f1 = hid[r1 + c0];
        float f2 = hid[r0 + c0 + 4], f3 = hid[r1 + c0 + 4];
        unsigned ah[4], al[4];
        ah[0] = f2tf32(f0); al[0] = f2tf32(f0 - __uint_as_float(ah[0]));
        ah[1] = f2tf32(f1); al[1] = f2tf32(f1 - __uint_as_float(ah[1]));
        ah[2] = f2tf32(f2); al[2] = f2tf32(f2 - __uint_as_float(ah[2]));
        ah[3] = f2tf32(f3); al[3] = f2tf32(f3 - __uint_as_float(ah[3]));
        const uint4* wrow = g_W2p + (kt * 8) * 32 + lane;
#pragma unroll
        for (int nt = 0; nt < 8; nt++) {
            uint4 w = __ldg(&wrow[nt * 32]);
            unsigned bh[2] = {w.x, w.y}, bl[2] = {w.z, w.w};
            mma8(acc2[nt], ah, bh);
            mma8(acc2[nt], ah, bl);
            mma8(acc2[nt], al, bh);
        }
    }

    // ---- write output ----
    {
        int node0 = nb + wm + g;
        int node1 = node0 + 8;
#pragma unroll
        for (int nt = 0; nt < 8; nt++) {
            int c = nt * 8 + 2 * t;
            if (node0 < N)
                *(float2*)(out + (size_t)node0 * FDIM + c) =
                    make_float2(acc2[nt][0], acc2[nt][1]);
            if (node1 < N)
                *(float2*)(out + (size_t)node1 * FDIM + c) =
                    make_float2(acc2[nt][2], acc2[nt][3]);
        }
    }
}

// ---------------------------------------------------------------------------
extern "C" void kernel_launch(void* const* d_in, const int* in_sizes, int n_in,
                              void* d_out, int out_size) {
    const float* x   = (const float*)d_in[0];
    const int*   ei  = (const int*)d_in[1];      // int32 (jax x64 disabled)
    const float* W1  = (const float*)d_in[2];
    const float* b1  = (const float*)d_in[3];
    const float* W2  = (const float*)d_in[4];
    const float* b2  = (const float*)d_in[5];
    const float* eps = (const float*)d_in[6];
    float* out = (float*)d_out;

    int N = in_sizes[0] / FDIM;       // 50000
    int E = in_sizes[1] / 2;          // 800000

    // REQUIRED: 67.6 KB dynamic smem exceeds the 48 KB default cap.
    cudaFuncSetAttribute(fused_mlp_kernel,
                         cudaFuncAttributeMaxDynamicSharedMemorySize,
                         SM_TOTAL_U32 * (int)sizeof(unsigned));

    // Zero both replicas with one async memset (graph-capturable, no alloc).
    void* hr_ptr = nullptr;
    cudaGetSymbolAddress(&hr_ptr, g_hr);
    cudaMemsetAsync(hr_ptr, 0,
                    (size_t)NREP * N_NODES_MAX * FDIM * sizeof(float));

    // Pack weights once into global scratch (overlaps with memset/scatter).
    pack_w_kernel<<<32, 256>>>(W1, W2);

    long long sthreads = (long long)E * 16;
    int sblocks = (int)((sthreads + 255) / 256);
    scatter_kernel<<<sblocks, 256>>>(x, ei, E);

    fused_mlp_kernel<<<(N + 127) / 128, 256, SM_TOTAL_U32 * sizeof(unsigned)>>>(
        x, b1, b2, eps, out, N);
}

// round 13
// speedup vs baseline: 3.3131x; 1.1887x over previous
#include <cuda_runtime.h>
#include <cstdint>

#define N_NODES_MAX 50000
#define FDIM 64
#define HDIM 128
#define NREP 2

// Scratch (no allocations allowed in kernel_launch)
__device__ __align__(16) float g_hr[NREP][(size_t)N_NODES_MAX * FDIM];
// bf16x3 weight fragments, b-frag order: uint4 = {bh0, bh1, bl0, bl1}
__device__ __align__(16) uint4 g_W1p[4 * 16 * 32];   // stage1: kt=4, nt=16
__device__ __align__(16) uint4 g_W2p[8 * 8 * 32];    // stage2: kt=8, nt=8

// ---------------------------------------------------------------------------
// Scatter-add with replica split: edge e accumulates into replica e&1.
// ---------------------------------------------------------------------------
__global__ void scatter_kernel(const float* __restrict__ x,
                               const int* __restrict__ ei, int E) {
    long long i = (long long)blockIdx.x * blockDim.x + threadIdx.x;
    if (i >= (long long)E * 16) return;
    int e = (int)(i >> 4);
    int c = (int)(i & 15);
    int row = ei[e];
    int col = ei[E + e];
    float4 v = *(const float4*)(x + (size_t)col * FDIM + c * 4);
    float* dst = g_hr[e & 1] + (size_t)row * FDIM + c * 4;
    asm volatile("red.global.add.v4.f32 [%0], {%1,%2,%3,%4};"
                 :: "l"(dst), "f"(v.x), "f"(v.y), "f"(v.z), "f"(v.w)
                 : "memory");
}

// ---------------------------------------------------------------------------
// bf16 helpers
// ---------------------------------------------------------------------------
__device__ __forceinline__ unsigned pack_bf16x2(float lo_elem, float hi_elem) {
    // low half <- lo_elem (smaller k index), high half <- hi_elem
    unsigned r;
    asm("cvt.rn.bf16x2.f32 %0, %1, %2;" : "=r"(r) : "f"(hi_elem), "f"(lo_elem));
    return r;
}
__device__ __forceinline__ float up_lo(unsigned w) {     // low bf16 -> f32
    return __uint_as_float(w << 16);
}
__device__ __forceinline__ float up_hi(unsigned w) {     // high bf16 -> f32
    return __uint_as_float(w & 0xffff0000u);
}

// Split pair (f0 at k, f1 at k+1) into hi word and lo-residual word.
__device__ __forceinline__ void split2(float f0, float f1,
                                       unsigned& hi, unsigned& lo) {
    hi = pack_bf16x2(f0, f1);
    lo = pack_bf16x2(f0 - up_lo(hi), f1 - up_hi(hi));
}

__device__ __forceinline__ void mma16(float* d, const unsigned* a, const unsigned* b) {
    asm volatile(
        "mma.sync.aligned.m16n8k16.row.col.f32.bf16.bf16.f32 "
        "{%0,%1,%2,%3}, {%4,%5,%6,%7}, {%8,%9}, {%0,%1,%2,%3};\n"
        : "+f"(d[0]), "+f"(d[1]), "+f"(d[2]), "+f"(d[3])
        : "r"(a[0]), "r"(a[1]), "r"(a[2]), "r"(a[3]), "r"(b[0]), "r"(b[1]));
}

// b-frag for k16: rows k0+2t,k0+2t+1 (b0) and k0+2t+8,k0+2t+9 (b1), col n.
__device__ __forceinline__ uint4 pack_bfrag(float f0, float f1, float f2, float f3) {
    uint4 u;
    unsigned h0, l0, h1, l1;
    split2(f0, f1, h0, l0);
    split2(f2, f3, h1, l1);
    u.x = h0; u.y = h1; u.z = l0; u.w = l1;
    return u;
}

// ---------------------------------------------------------------------------
// Prep: zero g_hr (all blocks) + pack W fragments (first 32 blocks).
// grid = 6250 x 256 threads; 1.6M float4 to zero.
// ---------------------------------------------------------------------------
__global__ void prep_kernel(const float* __restrict__ W1,
                            const float* __restrict__ W2, int n4) {
    int i = blockIdx.x * blockDim.x + threadIdx.x;
    if (i < n4) ((float4*)&g_hr[0][0])[i] = make_float4(0.f, 0.f, 0.f, 0.f);

    if (i < 4 * 16 * 32) {                 // W1 fragments
        int li = i & 31;
        int nt = (i >> 5) & 15;
        int kt = i >> 9;
        int t = li & 3, g = li >> 2;
        int n  = nt * 8 + g;
        int k0 = kt * 16 + 2 * t;
        g_W1p[i] = pack_bfrag(W1[k0 * HDIM + n],       W1[(k0 + 1) * HDIM + n],
                              W1[(k0 + 8) * HDIM + n], W1[(k0 + 9) * HDIM + n]);
    } else if (i < 4 * 16 * 32 + 8 * 8 * 32) {   // W2 fragments
        int j = i - 4 * 16 * 32;
        int li = j & 31;
        int nt = (j >> 5) & 7;
        int kt = j >> 8;
        int t = li & 3, g = li >> 2;
        int n  = nt * 8 + g;
        int k0 = kt * 16 + 2 * t;
        g_W2p[j] = pack_bfrag(W2[k0 * FDIM + n],       W2[(k0 + 1) * FDIM + n],
                              W2[(k0 + 8) * FDIM + n], W2[(k0 + 9) * FDIM + n]);
    }
}

// ---------------------------------------------------------------------------
// Fused MLP (bf16x3): out = relu(h@W1+b1)@W2 + b2, h = (1+eps)*x + agg0+agg1.
// 128 nodes/block, 256 threads = 8 warps, 1 m16 tile per warp.
// Activations pre-split into bf16 hi/lo words in smem -> inner loop is pure
// LDS + LDG + HMMA. Weights streamed from global pre-packed fragments.
// smem (u32): h_hi 128x36, h_lo 128x36 (stage1);
//             hid_hi 128x68, hid_lo 128x68 (stage2, aliased over h).
// ---------------------------------------------------------------------------
#define SH16  36          // (36 mod 32 == 4 -> conflict-free: 4g+t)
#define SHD16 68
#define H_HI  0
#define H_LO  (128 * SH16)            // 4608
#define HID_HI 0
#define HID_LO (128 * SHD16)          // 8704
#define SM_TOTAL_U32 (2 * 128 * SHD16)  // 17408 u32 = 69632 B

__global__ __launch_bounds__(256, 2)
void fused_mlp_kernel(const float* __restrict__ x,
                      const float* __restrict__ b1,
                      const float* __restrict__ b2,
                      const float* __restrict__ eps,
                      float* __restrict__ out, int N) {
    extern __shared__ unsigned smu[];

    const int tid  = threadIdx.x;
    const int lane = tid & 31;
    const int wid  = tid >> 5;
    const int g = lane >> 2;
    const int t = lane & 3;
    const int nb = blockIdx.x * 128;
    const int wm = wid * 16;

    // ---- load h tile, split to bf16 hi/lo ----
    {
        float s = 1.0f + __ldg(eps);
#pragma unroll 4
        for (int i = tid; i < 128 * 16; i += 256) {
            int r = i >> 4, c4 = i & 15;
            int node = nb + r;
            float4 v = make_float4(0.f, 0.f, 0.f, 0.f);
            if (node < N) {
                float4 a0 = ((const float4*)(g_hr[0] + (size_t)node * FDIM))[c4];
                float4 a1 = ((const float4*)(g_hr[1] + (size_t)node * FDIM))[c4];
                float4 xv = ((const float4*)(x       + (size_t)node * FDIM))[c4];
                v.x = fmaf(s, xv.x, a0.x + a1.x);
                v.y = fmaf(s, xv.y, a0.y + a1.y);
                v.z = fmaf(s, xv.z, a0.z + a1.z);
                v.w = fmaf(s, xv.w, a0.w + a1.w);
            }
            unsigned h0, l0, h1, l1;
            split2(v.x, v.y, h0, l0);
            split2(v.z, v.w, h1, l1);
            int base = r * SH16 + 2 * c4;
            smu[H_HI + base]     = h0;
            smu[H_HI + base + 1] = h1;
            smu[H_LO + base]     = l0;
            smu[H_LO + base + 1] = l1;
        }
    }
    __syncthreads();

    // =================== Stage 1: hid = relu(h @ W1 + b1) ===================
    float acc1[16][4];
#pragma unroll
    for (int nt = 0; nt < 16; nt++) {
        float2 bv = *(const float2*)(b1 + nt * 8 + 2 * t);
        acc1[nt][0] = bv.x; acc1[nt][1] = bv.y;
        acc1[nt][2] = bv.x; acc1[nt][3] = bv.y;
    }

#pragma unroll 1
    for (int kt = 0; kt < 4; kt++) {
        int r0 = (wm + g) * SH16;
        int r1 = (wm + g + 8) * SH16;
        int w0 = kt * 8 + t;
        int w1 = kt * 8 + 4 + t;
        unsigned ah[4], al[4];
        ah[0] = smu[H_HI + r0 + w0]; ah[1] = smu[H_HI + r1 + w0];
        ah[2] = smu[H_HI + r0 + w1]; ah[3] = smu[H_HI + r1 + w1];
        al[0] = smu[H_LO + r0 + w0]; al[1] = smu[H_LO + r1 + w0];
        al[2] = smu[H_LO + r0 + w1]; al[3] = smu[H_LO + r1 + w1];
        const uint4* wrow = g_W1p + (kt * 16) * 32 + lane;
#pragma unroll
        for (int nt = 0; nt < 16; nt++) {
            uint4 w = __ldg(&wrow[nt * 32]);
            unsigned bh[2] = {w.x, w.y}, bl[2] = {w.z, w.w};
            mma16(acc1[nt], ah, bh);    // hi*hi
            mma16(acc1[nt], ah, bl);    // hi*lo
            mma16(acc1[nt], al, bh);    // lo*hi
        }
    }

    __syncthreads();   // done reading h; safe to overwrite with hid

    {
        int r0 = (wm + g) * SHD16;
        int r1 = (wm + g + 8) * SHD16;
#pragma unroll
        for (int nt = 0; nt < 16; nt++) {
            int c = nt * 4 + t;
            float v0 = fmaxf(acc1[nt][0], 0.f), v1 = fmaxf(acc1[nt][1], 0.f);
            float v2 = fmaxf(acc1[nt][2], 0.f), v3 = fmaxf(acc1[nt][3], 0.f);
            unsigned h0, l0, h1, l1;
            split2(v0, v1, h0, l0);
            split2(v2, v3, h1, l1);
            smu[HID_HI + r0 + c] = h0;
            smu[HID_LO + r0 + c] = l0;
            smu[HID_HI + r1 + c] = h1;
            smu[HID_LO + r1 + c] = l1;
        }
    }
    __syncwarp();      // hid rows are warp-private

    // =================== Stage 2: out = hid @ W2 + b2 ===================
    float acc2[8][4];
#pragma unroll
    for (int nt = 0; nt < 8; nt++) {
        float2 bv = *(const float2*)(b2 + nt * 8 + 2 * t);
        acc2[nt][0] = bv.x; acc2[nt][1] = bv.y;
        acc2[nt][2] = bv.x; acc2[nt][3] = bv.y;
    }

#pragma unroll 1
    for (int kt = 0; kt < 8; kt++) {
        int r0 = (wm + g) * SHD16;
        int r1 = (wm + g + 8) * SHD16;
        int w0 = kt * 8 + t;
        int w1 = kt * 8 + 4 + t;
        unsigned ah[4], al[4];
        ah[0] = smu[HID_HI + r0 + w0]; ah[1] = smu[HID_HI + r1 + w0];
        ah[2] = smu[HID_HI + r0 + w1]; ah[3] = smu[HID_HI + r1 + w1];
        al[0] = smu[HID_LO + r0 + w0]; al[1] = smu[HID_LO + r1 + w0];
        al[2] = smu[HID_LO + r0 + w1]; al[3] = smu[HID_LO + r1 + w1];
        const uint4* wrow = g_W2p + (kt * 8) * 32 + lane;
#pragma unroll
        for (int nt = 0; nt < 8; nt++) {
            uint4 w = __ldg(&wrow[nt * 32]);
            unsigned bh[2] = {w.x, w.y}, bl[2] = {w.z, w.w};
            mma16(acc2[nt], ah, bh);
            mma16(acc2[nt], ah, bl);
            mma16(acc2[nt], al, bh);
        }
    }

    // ---- write output ----
    {
        int node0 = nb + wm + g;
        int node1 = node0 + 8;
#pragma unroll
        for (int nt = 0; nt < 8; nt++) {
            int c = nt * 8 + 2 * t;
            if (node0 < N)
                *(float2*)(out + (size_t)node0 * FDIM + c) =
                    make_float2(acc2[nt][0], acc2[nt][1]);
            if (node1 < N)
                *(float2*)(out + (size_t)node1 * FDIM + c) =
                    make_float2(acc2[nt][2], acc2[nt][3]);
        }
    }
}

// ---------------------------------------------------------------------------
extern "C" void kernel_launch(void* const* d_in, const int* in_sizes, int n_in,
                              void* d_out, int out_size) {
    const float* x   = (const float*)d_in[0];
    const int*   ei  = (const int*)d_in[1];      // int32 (jax x64 disabled)
    const float* W1  = (const float*)d_in[2];
    const float* b1  = (const float*)d_in[3];
    const float* W2  = (const float*)d_in[4];
    const float* b2  = (const float*)d_in[5];
    const float* eps = (const float*)d_in[6];
    float* out = (float*)d_out;

    int N = in_sizes[0] / FDIM;       // 50000
    int E = in_sizes[1] / 2;          // 800000

    // REQUIRED: 69.6 KB dynamic smem exceeds the 48 KB default cap.
    cudaFuncSetAttribute(fused_mlp_kernel,
                         cudaFuncAttributeMaxDynamicSharedMemorySize,
                         SM_TOTAL_U32 * (int)sizeof(unsigned));

    // Zero replicas + pack weight fragments in one kernel.
    int n4 = NREP * N_NODES_MAX * FDIM / 4;      // 1.6M float4
    prep_kernel<<<(n4 + 255) / 256, 256>>>(W1, W2, n4);

    long long sthreads = (long long)E * 16;
    int sblocks = (int)((sthreads + 255) / 256);
    scatter_kernel<<<sblocks, 256>>>(x, ei, E);

    fused_mlp_kernel<<<(N + 127) / 128, 256, SM_TOTAL_U32 * sizeof(unsigned)>>>(
        x, b1, b2, eps, out, N);
}

// round 14
// speedup vs baseline: 3.3523x; 1.0118x over previous
#include <cuda_runtime.h>
#include <cstdint>

#define N_NODES_MAX 50000
#define FDIM 64
#define HDIM 128
#define NREP 2

// Scratch (no allocations allowed in kernel_launch)
__device__ __align__(16) float g_hr[NREP][(size_t)N_NODES_MAX * FDIM];
// bf16x3 weight fragments, b-frag order: uint4 = {bh0, bh1, bl0, bl1}
__device__ __align__(16) uint4 g_W1p[4 * 16 * 32];   // stage1: kt=4, nt=16  (2048)
__device__ __align__(16) uint4 g_W2p[8 * 8 * 32];    // stage2: kt=8, nt=8   (2048)

// ---------------------------------------------------------------------------
// bf16 helpers
// ---------------------------------------------------------------------------
__device__ __forceinline__ unsigned pack_bf16x2(float lo_elem, float hi_elem) {
    unsigned r;
    asm("cvt.rn.bf16x2.f32 %0, %1, %2;" : "=r"(r) : "f"(hi_elem), "f"(lo_elem));
    return r;
}
__device__ __forceinline__ float up_lo(unsigned w) { return __uint_as_float(w << 16); }
__device__ __forceinline__ float up_hi(unsigned w) { return __uint_as_float(w & 0xffff0000u); }

__device__ __forceinline__ void split2(float f0, float f1,
                                       unsigned& hi, unsigned& lo) {
    hi = pack_bf16x2(f0, f1);
    lo = pack_bf16x2(f0 - up_lo(hi), f1 - up_hi(hi));
}

__device__ __forceinline__ void mma16(float* d, const unsigned* a, const unsigned* b) {
    asm volatile(
        "mma.sync.aligned.m16n8k16.row.col.f32.bf16.bf16.f32 "
        "{%0,%1,%2,%3}, {%4,%5,%6,%7}, {%8,%9}, {%0,%1,%2,%3};\n"
        : "+f"(d[0]), "+f"(d[1]), "+f"(d[2]), "+f"(d[3])
        : "r"(a[0]), "r"(a[1]), "r"(a[2]), "r"(a[3]), "r"(b[0]), "r"(b[1]));
}

__device__ __forceinline__ uint4 pack_bfrag(float f0, float f1, float f2, float f3) {
    uint4 u;
    unsigned h0, l0, h1, l1;
    split2(f0, f1, h0, l0);
    split2(f2, f3, h1, l1);
    u.x = h0; u.y = h1; u.z = l0; u.w = l1;
    return u;
}

// ---------------------------------------------------------------------------
// Scatter-add (replica split e&1) + weight-fragment packing piggybacked on
// the first 16 blocks (4096 threads; completes long before the MLP launches).
// ---------------------------------------------------------------------------
__global__ void scatter_kernel(const float* __restrict__ x,
                               const int* __restrict__ ei,
                               const float* __restrict__ W1,
                               const float* __restrict__ W2, int E) {
    long long i = (long long)blockIdx.x * blockDim.x + threadIdx.x;

    // --- piggyback: pack W1/W2 bf16 hi/lo fragments (one-off, tiny) ---
    if (i < 4096) {
        if (i < 2048) {                       // W1 fragments
            int idx = (int)i;
            int li = idx & 31;
            int nt = (idx >> 5) & 15;
            int kt = idx >> 9;
            int t = li & 3, g = li >> 2;
            int n  = nt * 8 + g;
            int k0 = kt * 16 + 2 * t;
            g_W1p[idx] = pack_bfrag(W1[k0 * HDIM + n],       W1[(k0 + 1) * HDIM + n],
                                    W1[(k0 + 8) * HDIM + n], W1[(k0 + 9) * HDIM + n]);
        } else {                              // W2 fragments
            int j = (int)i - 2048;
            int li = j & 31;
            int nt = (j >> 5) & 7;
            int kt = j >> 8;
            int t = li & 3, g = li >> 2;
            int n  = nt * 8 + g;
            int k0 = kt * 16 + 2 * t;
            g_W2p[j] = pack_bfrag(W2[k0 * FDIM + n],       W2[(k0 + 1) * FDIM + n],
                                  W2[(k0 + 8) * FDIM + n], W2[(k0 + 9) * FDIM + n]);
        }
    }

    // --- scatter work ---
    if (i >= (long long)E * 16) return;
    int e = (int)(i >> 4);
    int c = (int)(i & 15);
    int row = ei[e];
    int col = ei[E + e];
    float4 v = *(const float4*)(x + (size_t)col * FDIM + c * 4);
    float* dst = g_hr[e & 1] + (size_t)row * FDIM + c * 4;
    asm volatile("red.global.add.v4.f32 [%0], {%1,%2,%3,%4};"
                 :: "l"(dst), "f"(v.x), "f"(v.y), "f"(v.z), "f"(v.w)
                 : "memory");
}

// ---------------------------------------------------------------------------
// Fused MLP (bf16x3): out = relu(h@W1+b1)@W2 + b2, h = (1+eps)*x + agg0+agg1.
// 128 nodes/block, 256 threads = 8 warps, 1 m16 tile per warp.
// Activations pre-split into bf16 hi/lo words in smem -> inner loop is pure
// LDS + LDG + HMMA. Weights streamed from global pre-packed fragments.
// ---------------------------------------------------------------------------
#define SH16  36          // (36 mod 32 == 4 -> conflict-free: 4g+t)
#define SHD16 68
#define H_HI  0
#define H_LO  (128 * SH16)            // 4608
#define HID_HI 0
#define HID_LO (128 * SHD16)          // 8704
#define SM_TOTAL_U32 (2 * 128 * SHD16)  // 17408 u32 = 69632 B

__global__ __launch_bounds__(256, 2)
void fused_mlp_kernel(const float* __restrict__ x,
                      const float* __restrict__ b1,
                      const float* __restrict__ b2,
                      const float* __restrict__ eps,
                      float* __restrict__ out, int N) {
    extern __shared__ unsigned smu[];

    const int tid  = threadIdx.x;
    const int lane = tid & 31;
    const int wid  = tid >> 5;
    const int g = lane >> 2;
    const int t = lane & 3;
    const int nb = blockIdx.x * 128;
    const int wm = wid * 16;

    // ---- load h tile, split to bf16 hi/lo ----
    {
        float s = 1.0f + __ldg(eps);
#pragma unroll 4
        for (int i = tid; i < 128 * 16; i += 256) {
            int r = i >> 4, c4 = i & 15;
            int node = nb + r;
            float4 v = make_float4(0.f, 0.f, 0.f, 0.f);
            if (node < N) {
                float4 a0 = ((const float4*)(g_hr[0] + (size_t)node * FDIM))[c4];
                float4 a1 = ((const float4*)(g_hr[1] + (size_t)node * FDIM))[c4];
                float4 xv = ((const float4*)(x       + (size_t)node * FDIM))[c4];
                v.x = fmaf(s, xv.x, a0.x + a1.x);
                v.y = fmaf(s, xv.y, a0.y + a1.y);
                v.z = fmaf(s, xv.z, a0.z + a1.z);
                v.w = fmaf(s, xv.w, a0.w + a1.w);
            }
            unsigned h0, l0, h1, l1;
            split2(v.x, v.y, h0, l0);
            split2(v.z, v.w, h1, l1);
            int base = r * SH16 + 2 * c4;
            smu[H_HI + base]     = h0;
            smu[H_HI + base + 1] = h1;
            smu[H_LO + base]     = l0;
            smu[H_LO + base + 1] = l1;
        }
    }
    __syncthreads();

    // =================== Stage 1: hid = relu(h @ W1 + b1) ===================
    float acc1[16][4];
#pragma unroll
    for (int nt = 0; nt < 16; nt++) {
        float2 bv = *(const float2*)(b1 + nt * 8 + 2 * t);
        acc1[nt][0] = bv.x; acc1[nt][1] = bv.y;
        acc1[nt][2] = bv.x; acc1[nt][3] = bv.y;
    }

#pragma unroll 1
    for (int kt = 0; kt < 4; kt++) {
        int r0 = (wm + g) * SH16;
        int r1 = (wm + g + 8) * SH16;
        int w0 = kt * 8 + t;
        int w1 = kt * 8 + 4 + t;
        unsigned ah[4], al[4];
        ah[0] = smu[H_HI + r0 + w0]; ah[1] = smu[H_HI + r1 + w0];
        ah[2] = smu[H_HI + r0 + w1]; ah[3] = smu[H_HI + r1 + w1];
        al[0] = smu[H_LO + r0 + w0]; al[1] = smu[H_LO + r1 + w0];
        al[2] = smu[H_LO + r0 + w1]; al[3] = smu[H_LO + r1 + w1];
        const uint4* wrow = g_W1p + (kt * 16) * 32 + lane;
#pragma unroll
        for (int nt = 0; nt < 16; nt++) {
            uint4 w = __ldg(&wrow[nt * 32]);
            unsigned bh[2] = {w.x, w.y}, bl[2] = {w.z, w.w};
            mma16(acc1[nt], ah, bh);    // hi*hi
            mma16(acc1[nt], ah, bl);    // hi*lo
            mma16(acc1[nt], al, bh);    // lo*hi
        }
    }

    __syncthreads();   // done reading h; safe to overwrite with hid

    {
        int r0 = (wm + g) * SHD16;
        int r1 = (wm + g + 8) * SHD16;
#pragma unroll
        for (int nt = 0; nt < 16; nt++) {
            int c = nt * 4 + t;
            float v0 = fmaxf(acc1[nt][0], 0.f), v1 = fmaxf(acc1[nt][1], 0.f);
            float v2 = fmaxf(acc1[nt][2], 0.f), v3 = fmaxf(acc1[nt][3], 0.f);
            unsigned h0, l0, h1, l1;
            split2(v0, v1, h0, l0);
            split2(v2, v3, h1, l1);
            smu[HID_HI + r0 + c] = h0;
            smu[HID_LO + r0 + c] = l0;
            smu[HID_HI + r1 + c] = h1;
            smu[HID_LO + r1 + c] = l1;
        }
    }
    __syncwarp();      // hid rows are warp-private

    // =================== Stage 2: out = hid @ W2 + b2 ===================
    float acc2[8][4];
#pragma unroll
    for (int nt = 0; nt < 8; nt++) {
        float2 bv = *(const float2*)(b2 + nt * 8 + 2 * t);
        acc2[nt][0] = bv.x; acc2[nt][1] = bv.y;
        acc2[nt][2] = bv.x; acc2[nt][3] = bv.y;
    }

#pragma unroll 1
    for (int kt = 0; kt < 8; kt++) {
        int r0 = (wm + g) * SHD16;
        int r1 = (wm + g + 8) * SHD16;
        int w0 = kt * 8 + t;
        int w1 = kt * 8 + 4 + t;
        unsigned ah[4], al[4];
        ah[0] = smu[HID_HI + r0 + w0]; ah[1] = smu[HID_HI + r1 + w0];
        ah[2] = smu[HID_HI + r0 + w1]; ah[3] = smu[HID_HI + r1 + w1];
        al[0] = smu[HID_LO + r0 + w0]; al[1] = smu[HID_LO + r1 + w0];
        al[2] = smu[HID_LO + r0 + w1]; al[3] = smu[HID_LO + r1 + w1];
        const uint4* wrow = g_W2p + (kt * 8) * 32 + lane;
#pragma unroll
        for (int nt = 0; nt < 8; nt++) {
            uint4 w = __ldg(&wrow[nt * 32]);
            unsigned bh[2] = {w.x, w.y}, bl[2] = {w.z, w.w};
            mma16(acc2[nt], ah, bh);
            mma16(acc2[nt], ah, bl);
            mma16(acc2[nt], al, bh);
        }
    }

    // ---- write output ----
    {
        int node0 = nb + wm + g;
        int node1 = node0 + 8;
#pragma unroll
        for (int nt = 0; nt < 8; nt++) {
            int c = nt * 8 + 2 * t;
            if (node0 < N)
                *(float2*)(out + (size_t)node0 * FDIM + c) =
                    make_float2(acc2[nt][0], acc2[nt][1]);
            if (node1 < N)
                *(float2*)(out + (size_t)node1 * FDIM + c) =
                    make_float2(acc2[nt][2], acc2[nt][3]);
        }
    }
}

// ---------------------------------------------------------------------------
extern "C" void kernel_launch(void* const* d_in, const int* in_sizes, int n_in,
                              void* d_out, int out_size) {
    const float* x   = (const float*)d_in[0];
    const int*   ei  = (const int*)d_in[1];      // int32 (jax x64 disabled)
    const float* W1  = (const float*)d_in[2];
    const float* b1  = (const float*)d_in[3];
    const float* W2  = (const float*)d_in[4];
    const float* b2  = (const float*)d_in[5];
    const float* eps = (const float*)d_in[6];
    float* out = (float*)d_out;

    int N = in_sizes[0] / FDIM;       // 50000
    int E = in_sizes[1] / 2;          // 800000

    // REQUIRED: 69.6 KB dynamic smem exceeds the 48 KB default cap.
    cudaFuncSetAttribute(fused_mlp_kernel,
                         cudaFuncAttributeMaxDynamicSharedMemorySize,
                         SM_TOTAL_U32 * (int)sizeof(unsigned));

    // Zero both replicas with one async memset (graph-capturable, no alloc).
    void* hr_ptr = nullptr;
    cudaGetSymbolAddress(&hr_ptr, g_hr);
    cudaMemsetAsync(hr_ptr, 0,
                    (size_t)NREP * N_NODES_MAX * FDIM * sizeof(float));

    // Scatter (+ weight packing piggybacked on the first 16 blocks).
    long long sthreads = (long long)E * 16;
    int sblocks = (int)((sthreads + 255) / 256);
    scatter_kernel<<<sblocks, 256>>>(x, ei, W1, W2, E);

    fused_mlp_kernel<<<(N + 127) / 128, 256, SM_TOTAL_U32 * sizeof(unsigned)>>>(
        x, b1, b2, eps, out, N);
}

// round 16
// speedup vs baseline: 3.3645x; 1.0036x over previous
#include <cuda_runtime.h>
#include <cstdint>

#define N_NODES_MAX 50000
#define FDIM 64
#define HDIM 128
#define NREP 2

// Scratch (no allocations allowed in kernel_launch)
__device__ __align__(16) float g_hr[NREP][(size_t)N_NODES_MAX * FDIM];
// bf16x3 weight fragments, b-frag order: uint4 = {bh0, bh1, bl0, bl1}
__device__ __align__(16) uint4 g_W1p[4 * 16 * 32];   // stage1: kt=4, nt=16  (2048)
__device__ __align__(16) uint4 g_W2p[8 * 8 * 32];    // stage2: kt=8, nt=8   (2048)

// ---------------------------------------------------------------------------
// bf16 helpers
// ---------------------------------------------------------------------------
__device__ __forceinline__ unsigned pack_bf16x2(float lo_elem, float hi_elem) {
    unsigned r;
    asm("cvt.rn.bf16x2.f32 %0, %1, %2;" : "=r"(r) : "f"(hi_elem), "f"(lo_elem));
    return r;
}
__device__ __forceinline__ float up_lo(unsigned w) { return __uint_as_float(w << 16); }
__device__ __forceinline__ float up_hi(unsigned w) { return __uint_as_float(w & 0xffff0000u); }

__device__ __forceinline__ void split2(float f0, float f1,
                                       unsigned& hi, unsigned& lo) {
    hi = pack_bf16x2(f0, f1);
    lo = pack_bf16x2(f0 - up_lo(hi), f1 - up_hi(hi));
}

__device__ __forceinline__ void mma16(float* d, const unsigned* a, const unsigned* b) {
    asm volatile(
        "mma.sync.aligned.m16n8k16.row.col.f32.bf16.bf16.f32 "
        "{%0,%1,%2,%3}, {%4,%5,%6,%7}, {%8,%9}, {%0,%1,%2,%3};\n"
        : "+f"(d[0]), "+f"(d[1]), "+f"(d[2]), "+f"(d[3])
        : "r"(a[0]), "r"(a[1]), "r"(a[2]), "r"(a[3]), "r"(b[0]), "r"(b[1]));
}

__device__ __forceinline__ uint4 pack_bfrag(float f0, float f1, float f2, float f3) {
    uint4 u;
    unsigned h0, l0, h1, l1;
    split2(f0, f1, h0, l0);
    split2(f2, f3, h1, l1);
    u.x = h0; u.y = h1; u.z = l0; u.w = l1;
    return u;
}

// ---------------------------------------------------------------------------
// Scatter-add (replica split e&1) + weight-fragment packing piggybacked on
// the first 16 blocks.
// ---------------------------------------------------------------------------
__global__ void scatter_kernel(const float* __restrict__ x,
                               const int* __restrict__ ei,
                               const float* __restrict__ W1,
                               const float* __restrict__ W2, int E) {
    long long i = (long long)blockIdx.x * blockDim.x + threadIdx.x;

    if (i < 4096) {
        if (i < 2048) {                       // W1 fragments
            int idx = (int)i;
            int li = idx & 31;
            int nt = (idx >> 5) & 15;
            int kt = idx >> 9;
            int t = li & 3, g = li >> 2;
            int n  = nt * 8 + g;
            int k0 = kt * 16 + 2 * t;
            g_W1p[idx] = pack_bfrag(W1[k0 * HDIM + n],       W1[(k0 + 1) * HDIM + n],
                                    W1[(k0 + 8) * HDIM + n], W1[(k0 + 9) * HDIM + n]);
        } else {                              // W2 fragments
            int j = (int)i - 2048;
            int li = j & 31;
            int nt = (j >> 5) & 7;
            int kt = j >> 8;
            int t = li & 3, g = li >> 2;
            int n  = nt * 8 + g;
            int k0 = kt * 16 + 2 * t;
            g_W2p[j] = pack_bfrag(W2[k0 * FDIM + n],       W2[(k0 + 1) * FDIM + n],
                                  W2[(k0 + 8) * FDIM + n], W2[(k0 + 9) * FDIM + n]);
        }
    }

    if (i >= (long long)E * 16) return;
    int e = (int)(i >> 4);
    int c = (int)(i & 15);
    int row = ei[e];
    int col = ei[E + e];
    float4 v = *(const float4*)(x + (size_t)col * FDIM + c * 4);
    float* dst = g_hr[e & 1] + (size_t)row * FDIM + c * 4;
    asm volatile("red.global.add.v4.f32 [%0], {%1,%2,%3,%4};"
                 :: "l"(dst), "f"(v.x), "f"(v.y), "f"(v.z), "f"(v.w)
                 : "memory");
}

// ---------------------------------------------------------------------------
// Fused MLP (bf16x3). 128 nodes/block, 256 threads = 8 warps.
// kt loops UNROLLED so ptxas pipelines weight LDGs across iterations;
// compensation MMAs interleaved across nt pairs to break RAW chains.
// ---------------------------------------------------------------------------
#define SH16  36
#define SHD16 68
#define H_HI  0
#define H_LO  (128 * SH16)
#define HID_HI 0
#define HID_LO (128 * SHD16)
#define SM_TOTAL_U32 (2 * 128 * SHD16)  // 17408 u32 = 69632 B

__global__ __launch_bounds__(256, 2)
void fused_mlp_kernel(const float* __restrict__ x,
                      const float* __restrict__ b1,
                      const float* __restrict__ b2,
                      const float* __restrict__ eps,
                      float* __restrict__ out, int N) {
    extern __shared__ unsigned smu[];

    const int tid  = threadIdx.x;
    const int lane = tid & 31;
    const int wid  = tid >> 5;
    const int g = lane >> 2;
    const int t = lane & 3;
    const int nb = blockIdx.x * 128;
    const int wm = wid * 16;

    // ---- bias preload (overlaps with h-load LDG stream) ----
    float2 bv1[16], bv2[8];
#pragma unroll
    for (int nt = 0; nt < 16; nt++) bv1[nt] = *(const float2*)(b1 + nt * 8 + 2 * t);
#pragma unroll
    for (int nt = 0; nt < 8; nt++)  bv2[nt] = *(const float2*)(b2 + nt * 8 + 2 * t);

    // ---- load h tile, split to bf16 hi/lo ----
    {
        float s = 1.0f + __ldg(eps);
#pragma unroll 4
        for (int i = tid; i < 128 * 16; i += 256) {
            int r = i >> 4, c4 = i & 15;
            int node = nb + r;
            float4 v = make_float4(0.f, 0.f, 0.f, 0.f);
            if (node < N) {
                float4 a0 = ((const float4*)(g_hr[0] + (size_t)node * FDIM))[c4];
                float4 a1 = ((const float4*)(g_hr[1] + (size_t)node * FDIM))[c4];
                float4 xv = ((const float4*)(x       + (size_t)node * FDIM))[c4];
                v.x = fmaf(s, xv.x, a0.x + a1.x);
                v.y = fmaf(s, xv.y, a0.y + a1.y);
                v.z = fmaf(s, xv.z, a0.z + a1.z);
                v.w = fmaf(s, xv.w, a0.w + a1.w);
            }
            unsigned h0, l0, h1, l1;
            split2(v.x, v.y, h0, l0);
            split2(v.z, v.w, h1, l1);
            int base = r * SH16 + 2 * c4;
            smu[H_HI + base]     = h0;
            smu[H_HI + base + 1] = h1;
            smu[H_LO + base]     = l0;
            smu[H_LO + base + 1] = l1;
        }
    }
    __syncthreads();

    // =================== Stage 1: hid = relu(h @ W1 + b1) ===================
    float acc1[16][4];
#pragma unroll
    for (int nt = 0; nt < 16; nt++) {
        acc1[nt][0] = bv1[nt].x; acc1[nt][1] = bv1[nt].y;
        acc1[nt][2] = bv1[nt].x; acc1[nt][3] = bv1[nt].y;
    }

#pragma unroll
    for (int kt = 0; kt < 4; kt++) {
        int r0 = (wm + g) * SH16;
        int r1 = (wm + g + 8) * SH16;
        int w0 = kt * 8 + t;
        int w1 = kt * 8 + 4 + t;
        unsigned ah[4], al[4];
        ah[0] = smu[H_HI + r0 + w0]; ah[1] = smu[H_HI + r1 + w0];
        ah[2] = smu[H_HI + r0 + w1]; ah[3] = smu[H_HI + r1 + w1];
        al[0] = smu[H_LO + r0 + w0]; al[1] = smu[H_LO + r1 + w0];
        al[2] = smu[H_LO + r0 + w1]; al[3] = smu[H_LO + r1 + w1];
        const uint4* wrow = g_W1p + (kt * 16) * 32 + lane;
        // process nt in pairs: two independent accumulator chains per window
#pragma unroll
        for (int np = 0; np < 8; np++) {
            int na = 2 * np, nc = 2 * np + 1;
            uint4 wa = __ldg(&wrow[na * 32]);
            uint4 wc = __ldg(&wrow[nc * 32]);
            unsigned bha[2] = {wa.x, wa.y}, bla[2] = {wa.z, wa.w};
            unsigned bhc[2] = {wc.x, wc.y}, blc[2] = {wc.z, wc.w};
            mma16(acc1[na], ah, bha);
            mma16(acc1[nc], ah, bhc);
            mma16(acc1[na], ah, bla);
            mma16(acc1[nc], ah, blc);
            mma16(acc1[na], al, bha);
            mma16(acc1[nc], al, bhc);
        }
    }

    __syncthreads();   // done reading h; safe to overwrite with hid

    {
        int r0 = (wm + g) * SHD16;
        int r1 = (wm + g + 8) * SHD16;
#pragma unroll
        for (int nt = 0; nt < 16; nt++) {
            int c = nt * 4 + t;
            float v0 = fmaxf(acc1[nt][0], 0.f), v1 = fmaxf(acc1[nt][1], 0.f);
            float v2 = fmaxf(acc1[nt][2], 0.f), v3 = fmaxf(acc1[nt][3], 0.f);
            unsigned h0, l0, h1, l1;
            split2(v0, v1, h0, l0);
            split2(v2, v3, h1, l1);
            smu[HID_HI + r0 + c] = h0;
            smu[HID_LO + r0 + c] = l0;
            smu[HID_HI + r1 + c] = h1;
            smu[HID_LO + r1 + c] = l1;
        }
    }
    __syncwarp();      // hid rows are warp-private

    // =================== Stage 2: out = hid @ W2 + b2 ===================
    float acc2[8][4];
#pragma unroll
    for (int nt = 0; nt < 8; nt++) {
        acc2[nt][0] = bv2[nt].x; acc2[nt][1] = bv2[nt].y;
        acc2[nt][2] = bv2[nt].x; acc2[nt][3] = bv2[nt].y;
    }

#pragma unroll 2
    for (int kt = 0; kt < 8; kt++) {
        int r0 = (wm + g) * SHD16;
        int r1 = (wm + g + 8) * SHD16;
        int w0 = kt * 8 + t;
        int w1 = kt * 8 + 4 + t;
        unsigned ah[4], al[4];
        ah[0] = smu[HID_HI + r0 + w0]; ah[1] = smu[HID_HI + r1 + w0];
        ah[2] = smu[HID_HI + r0 + w1]; ah[3] = smu[HID_HI + r1 + w1];
        al[0] = smu[HID_LO + r0 + w0]; al[1] = smu[HID_LO + r1 + w0];
        al[2] = smu[HID_LO + r0 + w1]; al[3] = smu[HID_LO + r1 + w1];
        const uint4* wrow = g_W2p + (kt * 8) * 32 + lane;
#pragma unroll
        for (int np = 0; np < 4; np++) {
            int na = 2 * np, nc = 2 * np + 1;
            uint4 wa = __ldg(&wrow[na * 32]);
            uint4 wc = __ldg(&wrow[nc * 32]);
            unsigned bha[2] = {wa.x, wa.y}, bla[2] = {wa.z, wa.w};
            unsigned bhc[2] = {wc.x, wc.y}, blc[2] = {wc.z, wc.w};
            mma16(acc2[na], ah, bha);
            mma16(acc2[nc], ah, bhc);
            mma16(acc2[na], ah, bla);
            mma16(acc2[nc], ah, blc);
            mma16(acc2[na], al, bha);
            mma16(acc2[nc], al, bhc);
        }
    }

    // ---- write output ----
    {
        int node0 = nb + wm + g;
        int node1 = node0 + 8;
#pragma unroll
        for (int nt = 0; nt < 8; nt++) {
            int c = nt * 8 + 2 * t;
            if (node0 < N)
                *(float2*)(out + (size_t)node0 * FDIM + c) =
                    make_float2(acc2[nt][0], acc2[nt][1]);
            if (node1 < N)
                *(float2*)(out + (size_t)node1 * FDIM + c) =
                    make_float2(acc2[nt][2], acc2[nt][3]);
        }
    }
}

// ---------------------------------------------------------------------------
extern "C" void kernel_launch(void* const* d_in, const int* in_sizes, int n_in,
                              void* d_out, int out_size) {
    const float* x   = (const float*)d_in[0];
    const int*   ei  = (const int*)d_in[1];      // int32 (jax x64 disabled)
    const float* W1  = (const float*)d_in[2];
    const float* b1  = (const float*)d_in[3];
    const float* W2  = (const float*)d_in[4];
    const float* b2  = (const float*)d_in[5];
    const float* eps = (const float*)d_in[6];
    float* out = (float*)d_out;

    int N = in_sizes[0] / FDIM;       // 50000
    int E = in_sizes[1] / 2;          // 800000

    // REQUIRED: 69.6 KB dynamic smem exceeds the 48 KB default cap.
    cudaFuncSetAttribute(fused_mlp_kernel,
                         cudaFuncAttributeMaxDynamicSharedMemorySize,
                         SM_TOTAL_U32 * (int)sizeof(unsigned));

    // Zero both replicas with one async memset (graph-capturable, no alloc).
    void* hr_ptr = nullptr;
    cudaGetSymbolAddress(&hr_ptr, g_hr);
    cudaMemsetAsync(hr_ptr, 0,
                    (size_t)NREP * N_NODES_MAX * FDIM * sizeof(float));

    // Scatter (+ weight packing piggybacked on the first 16 blocks).
    long long sthreads = (long long)E * 16;
    int sblocks = (int)((sthreads + 255) / 256);
    scatter_kernel<<<sblocks, 256>>>(x, ei, W1, W2, E);

    fused_mlp_kernel<<<(N + 127) / 128, 256, SM_TOTAL_U32 * sizeof(unsigned)>>>(
        x, b1, b2, eps, out, N);
}